// round 12
// baseline (speedup 1.0000x reference)
#include <cuda_runtime.h>
#include <math.h>

// PCEN, exact chunked linear-scan formulation.
//   ema_t = w*x_t + (1-w)*ema_{t-1}, ema_0 = x_0
//   out   = (x/(1e-6+ema)^a + delta)^(1/r) - delta^(1/r)
// x [B,T,C] fp32, params [C]. B=64, T=4096, C=80. float2 across channels.
//
// Decay u = 1-w is per-channel constant, so chunk composition is
//   s_out = u^CHUNK * s_in + b_chunk,  b_chunk = sum_i u^(CHUNK-1-i)*w*x_i.
// K1 computes b_chunk per (row, chunk) -> 1.25MB scratch.
// K2 Horner-combines preceding folds (A = u^CHUNK) for the exact incoming
// state, then runs the 64-step EMA + PCEN transform. No approximation beyond
// MUFU ex2/lg2/rsqrt (~1e-6).

#define TB 64
#define TT 4096
#define TC 80
#define C2 (TC / 2)             // 40 float2 lanes per row
#define ROWS (TB * C2)          // 2560
#define CHUNK 64
#define NCHUNK (TT / CHUNK)     // 64
#define FLOOR_C 1e-6f
#define BLOCK 128
#define UNB 8                   // load-batch depth (double-buffered)

__device__ float2 g_fold[(size_t)ROWS * NCHUNK];   // [row][chunk], 1.25 MB

__device__ __forceinline__ float ex2(float v){ float r; asm("ex2.approx.ftz.f32 %0,%1;" : "=f"(r) : "f"(v)); return r; }
__device__ __forceinline__ float lg2(float v){ float r; asm("lg2.approx.ftz.f32 %0,%1;" : "=f"(r) : "f"(v)); return r; }
__device__ __forceinline__ float rsq(float v){ float r; asm("rsqrt.approx.ftz.f32 %0,%1;" : "=f"(r) : "f"(v)); return r; }

// ---------------- K1: per-chunk fold ----------------
__global__ void __launch_bounds__(BLOCK, 8)
pcen_fold_kernel(const float* __restrict__ x, const float* __restrict__ smooth)
{
    int gid   = blockIdx.x * BLOCK + threadIdx.x;     // TOTAL = ROWS*NCHUNK
    int chunk = gid / ROWS;                           // block-uniform
    int r     = gid - chunk * ROWS;
    int b     = r / C2, c2 = r - b * C2;

    float2 sm = ((const float2*)smooth)[c2];
    float wx = fminf(fmaxf(sm.x, 0.f), 1.f), wy = fminf(fmaxf(sm.y, 0.f), 1.f);
    float ux = 1.f - wx,                     uy = 1.f - wy;

    const float2* xp = (const float2*)(x + (size_t)b * TT * TC) + c2
                       + (size_t)chunk * CHUNK * C2;

    float2 cur[UNB], nxt[UNB];
    #pragma unroll
    for (int i = 0; i < UNB; ++i) cur[i] = __ldg(xp + (size_t)i * C2);

    // chunk 0 folds the init (s = x0; first update is idempotent since u+w=1)
    float sx, sy;
    if (chunk == 0) { sx = cur[0].x; sy = cur[0].y; }
    else            { sx = 0.f;      sy = 0.f;      }

    #pragma unroll 1
    for (int bi = 1; bi < CHUNK / UNB; ++bi) {
        const float2* q = xp + (size_t)bi * UNB * C2;
        #pragma unroll
        for (int i = 0; i < UNB; ++i) nxt[i] = __ldg(q + (size_t)i * C2);
        #pragma unroll
        for (int i = 0; i < UNB; ++i) {
            sx = fmaf(ux, sx, wx * cur[i].x);
            sy = fmaf(uy, sy, wy * cur[i].y);
        }
        #pragma unroll
        for (int i = 0; i < UNB; ++i) cur[i] = nxt[i];
    }
    #pragma unroll
    for (int i = 0; i < UNB; ++i) {
        sx = fmaf(ux, sx, wx * cur[i].x);
        sy = fmaf(uy, sy, wy * cur[i].y);
    }
    float2 o; o.x = sx; o.y = sy;
    g_fold[(size_t)r * NCHUNK + chunk] = o;
}

// ---------------- K2: combine + apply ----------------
template <bool IS_SQRT>
__device__ __forceinline__ void pcen_step(
    float2 v, float& ema_x, float& ema_y,
    float wx, float wy, float ux, float uy,
    float nax, float nay, float dx, float dy,
    float irx, float iry, float dpx, float dpy, float2& o)
{
    ema_x = fmaf(ux, ema_x, wx * v.x);
    ema_y = fmaf(uy, ema_y, wy * v.y);
    float px = ex2(nax * lg2(ema_x + FLOOR_C));   // base^(-a)
    float py = ex2(nay * lg2(ema_y + FLOOR_C));
    float yx = fmaf(v.x, px, dx);                 // x*base^(-a) + delta
    float yy = fmaf(v.y, py, dy);
    float ox, oy;
    if (IS_SQRT) { ox = yx * rsq(yx); oy = yy * rsq(yy); }   // sqrt(y)
    else         { ox = ex2(irx * lg2(yx)); oy = ex2(iry * lg2(yy)); }
    o.x = ox - dpx;
    o.y = oy - dpy;
}

template <bool IS_SQRT>
__device__ __forceinline__ void apply_sweep(
    const float2* __restrict__ pm, float2* __restrict__ po,
    float ema_x, float ema_y,
    float wx, float wy, float ux, float uy, float nax, float nay,
    float dx, float dy, float irx, float iry, float dpx, float dpy)
{
    float2 cur[UNB], nxt[UNB];
    #pragma unroll
    for (int i = 0; i < UNB; ++i) cur[i] = __ldg(pm + (size_t)i * C2);

    #pragma unroll 1
    for (int bi = 1; bi < CHUNK / UNB; ++bi) {
        const float2* q = pm + (size_t)bi * UNB * C2;
        #pragma unroll
        for (int i = 0; i < UNB; ++i) nxt[i] = __ldg(q + (size_t)i * C2);

        float2* w = po + (size_t)(bi - 1) * UNB * C2;
        #pragma unroll
        for (int i = 0; i < UNB; ++i) {
            float2 o;
            pcen_step<IS_SQRT>(cur[i], ema_x, ema_y, wx, wy, ux, uy,
                               nax, nay, dx, dy, irx, iry, dpx, dpy, o);
            w[(size_t)i * C2] = o;
        }
        #pragma unroll
        for (int i = 0; i < UNB; ++i) cur[i] = nxt[i];
    }
    float2* w = po + (size_t)(CHUNK / UNB - 1) * UNB * C2;
    #pragma unroll
    for (int i = 0; i < UNB; ++i) {
        float2 o;
        pcen_step<IS_SQRT>(cur[i], ema_x, ema_y, wx, wy, ux, uy,
                           nax, nay, dx, dy, irx, iry, dpx, dpy, o);
        w[(size_t)i * C2] = o;
    }
}

__global__ void __launch_bounds__(BLOCK, 8)
pcen_apply_kernel(const float* __restrict__ x,
                  const float* __restrict__ alpha,
                  const float* __restrict__ delta,
                  const float* __restrict__ root,
                  const float* __restrict__ smooth,
                  float* __restrict__ out)
{
    int gid   = blockIdx.x * BLOCK + threadIdx.x;
    int chunk = gid / ROWS;                           // block-uniform
    int r     = gid - chunk * ROWS;
    int b     = r / C2, c2 = r - b * C2;

    float2 sm = ((const float2*)smooth)[c2];
    float2 al = ((const float2*)alpha)[c2];
    float2 rt = ((const float2*)root)[c2];
    float2 dl = ((const float2*)delta)[c2];
    float wx = fminf(fmaxf(sm.x, 0.f), 1.f), wy = fminf(fmaxf(sm.y, 0.f), 1.f);
    float ux = 1.f - wx,                     uy = 1.f - wy;
    float nax = -fminf(al.x, 1.f),           nay = -fminf(al.y, 1.f);
    float rx = fmaxf(rt.x, 1.f),             ry = fmaxf(rt.y, 1.f);
    float irx = 1.f / rx,                    iry = 1.f / ry;
    float dpx = ex2(irx * lg2(dl.x));        // delta^(1/r), delta > 0 here
    float dpy = ex2(iry * lg2(dl.y));
    bool is_sqrt = (rx == 2.0f) && (ry == 2.0f);

    // A = u^CHUNK via 6 squarings (CHUNK = 64)
    float Ax = ux, Ay = uy;
    #pragma unroll
    for (int i = 0; i < 6; ++i) { Ax *= Ax; Ay *= Ay; }

    const float2* xp = (const float2*)(x   + (size_t)b * TT * TC) + c2
                       + (size_t)chunk * CHUNK * C2;
    float2*       op = (float2*)      (out + (size_t)b * TT * TC) + c2
                       + (size_t)chunk * CHUNK * C2;

    float ema_x, ema_y;
    if (chunk == 0) {
        float2 x0 = __ldg(xp);
        ema_x = x0.x; ema_y = x0.y;          // first step idempotent => ema_0 = x_0
    } else {
        // exact incoming state: Horner over preceding folds, A-weighted.
        const float2* fp = g_fold + (size_t)r * NCHUNK;
        float2 f0 = __ldg(fp);
        ema_x = f0.x; ema_y = f0.y;
        int j = 1;
        float2 buf[UNB];
        #pragma unroll 1
        while (j + UNB <= chunk) {           // batch-prefetch (L2-resident scratch)
            #pragma unroll
            for (int i = 0; i < UNB; ++i) buf[i] = __ldg(fp + j + i);
            #pragma unroll
            for (int i = 0; i < UNB; ++i) {
                ema_x = fmaf(Ax, ema_x, buf[i].x);
                ema_y = fmaf(Ay, ema_y, buf[i].y);
            }
            j += UNB;
        }
        #pragma unroll 1
        for (; j < chunk; ++j) {
            float2 v = __ldg(fp + j);
            ema_x = fmaf(Ax, ema_x, v.x);
            ema_y = fmaf(Ay, ema_y, v.y);
        }
    }

    if (is_sqrt)
        apply_sweep<true >(xp, op, ema_x, ema_y, wx, wy, ux, uy, nax, nay,
                           dl.x, dl.y, irx, iry, dpx, dpy);
    else
        apply_sweep<false>(xp, op, ema_x, ema_y, wx, wy, ux, uy, nax, nay,
                           dl.x, dl.y, irx, iry, dpx, dpy);
}

extern "C" void kernel_launch(void* const* d_in, const int* in_sizes, int n_in,
                              void* d_out, int out_size)
{
    const float* x      = (const float*)d_in[0];
    const float* alpha  = (const float*)d_in[1];
    const float* delta  = (const float*)d_in[2];
    const float* root   = (const float*)d_in[3];
    const float* smooth = (const float*)d_in[4];
    float* out = (float*)d_out;

    const int total = ROWS * NCHUNK;           // 163840 threads
    dim3 grid(total / BLOCK);                  // 1280 blocks
    pcen_fold_kernel <<<grid, BLOCK>>>(x, smooth);
    pcen_apply_kernel<<<grid, BLOCK>>>(x, alpha, delta, root, smooth, out);
}